// round 1
// baseline (speedup 1.0000x reference)
#include <cuda_runtime.h>

// PANLoss on GB300: single-pass streaming reduction.
// Inputs (metadata order):
//   0 pred_regions   (16,1,640,640) f32
//   1 regions_gt     (16,1,640,640) f32
//   2 pred_kernels   (16,1,640,640) f32
//   3 kernels_gt     (16,1,640,640) f32
//   4 pred_similarities (16,4,640,640) f32
//   5 text_mask_ndi_labels   (16,640,640) i32  in [0,8]
//   6 kernel_mask_ndi_labels (16,640,640) i32  in [0,8]
// Output: 5 f32 scalars (loss, loss_regions, loss_kernel, loss_agg, loss_dis)

#define HWPX  409600
#define HW4   102400
#define NB    16
#define BPB   27          // blocks per batch (27*16 = 432 blocks, ~one wave)
#define NTH   256
#define NSEG  9
#define NBIN  81          // (t,k) pair bins
#define SSTR  192         // scratch stride per batch (81+81+6 = 168, padded)
#define EPSF  1e-5f

__device__ float g_scratch[NB * SSTR];

__device__ __forceinline__ float fast_sigmoid(float x) {
    float e = __expf(-x);          // FMUL + MUFU.EX2
    float d = 1.0f + e;
    float r;
    asm("rcp.approx.ftz.f32 %0, %1;" : "=f"(r) : "f"(d));  // MUFU.RCP
    return r;
}

__global__ void pan_zero() {
    for (int i = threadIdx.x; i < NB * SSTR; i += blockDim.x)
        g_scratch[i] = 0.0f;
}

__global__ __launch_bounds__(NTH) void pan_main(
    const float4* __restrict__ pr, const float4* __restrict__ rg,
    const float4* __restrict__ pk, const float4* __restrict__ kg,
    const float4* __restrict__ sim,
    const int4* __restrict__ tl, const int4* __restrict__ kl)
{
    __shared__ float sm[2 * NBIN + 6];
    const int b   = blockIdx.y;
    const int tid = threadIdx.x;

    for (int i = tid; i < 2 * NBIN + 6; i += NTH) sm[i] = 0.0f;
    __syncthreads();

    const float4* __restrict__ prb = pr + (size_t)b * HW4;
    const float4* __restrict__ rgb = rg + (size_t)b * HW4;
    const float4* __restrict__ pkb = pk + (size_t)b * HW4;
    const float4* __restrict__ kgb = kg + (size_t)b * HW4;
    const float4* __restrict__ smb = sim + (size_t)b * 4 * HW4;
    const int4*   __restrict__ tlb = tl + (size_t)b * HW4;
    const int4*   __restrict__ klb = kl + (size_t)b * HW4;

    float ir = 0.f, prr = 0.f, grr = 0.f;   // region dice: sum p*g, p*p, g*g
    float ik = 0.f, pkk = 0.f, gkk = 0.f;   // kernel dice

    for (int g = blockIdx.x * NTH + tid; g < HW4; g += BPB * NTH) {
        float4 A  = prb[g];
        float4 G  = rgb[g];
        float4 C  = pkb[g];
        float4 D  = kgb[g];
        float4 S0 = smb[g];
        float4 S1 = smb[HW4 + g];
        float4 S2 = smb[2 * HW4 + g];
        float4 S3 = smb[3 * HW4 + g];
        int4   T  = tlb[g];
        int4   K  = klb[g];

#define PAN_PROC(ax, gx, cx, dx, s0x, s1x, s2x, s3x, tx, kx) do {          \
        float p_ = fast_sigmoid(ax);                                       \
        ir  = fmaf(p_, (gx), ir);                                          \
        prr = fmaf(p_, p_, prr);                                           \
        grr = fmaf((gx), (gx), grr);                                       \
        float q_ = fast_sigmoid(cx);                                       \
        ik  = fmaf(q_, (dx), ik);                                          \
        pkk = fmaf(q_, q_, pkk);                                           \
        gkk = fmaf((dx), (dx), gkk);                                       \
        float s2_ = fmaf((s0x),(s0x), fmaf((s1x),(s1x),                    \
                    fmaf((s2x),(s2x), (s3x)*(s3x))));                      \
        int bin_ = (tx) * NSEG + (kx);                                     \
        atomicAdd(&sm[bin_], s2_);                                         \
        atomicAdd(&sm[NBIN + bin_], 1.0f);                                 \
    } while (0)

        PAN_PROC(A.x, G.x, C.x, D.x, S0.x, S1.x, S2.x, S3.x, T.x, K.x);
        PAN_PROC(A.y, G.y, C.y, D.y, S0.y, S1.y, S2.y, S3.y, T.y, K.y);
        PAN_PROC(A.z, G.z, C.z, D.z, S0.z, S1.z, S2.z, S3.z, T.z, K.z);
        PAN_PROC(A.w, G.w, C.w, D.w, S0.w, S1.w, S2.w, S3.w, T.w, K.w);
#undef PAN_PROC
    }

    // Warp-reduce the 6 dice accumulators, then one shared atomic per warp.
    #pragma unroll
    for (int o = 16; o; o >>= 1) {
        ir  += __shfl_down_sync(0xffffffffu, ir,  o);
        prr += __shfl_down_sync(0xffffffffu, prr, o);
        grr += __shfl_down_sync(0xffffffffu, grr, o);
        ik  += __shfl_down_sync(0xffffffffu, ik,  o);
        pkk += __shfl_down_sync(0xffffffffu, pkk, o);
        gkk += __shfl_down_sync(0xffffffffu, gkk, o);
    }
    if ((tid & 31) == 0) {
        atomicAdd(&sm[2 * NBIN + 0], ir);
        atomicAdd(&sm[2 * NBIN + 1], prr);
        atomicAdd(&sm[2 * NBIN + 2], grr);
        atomicAdd(&sm[2 * NBIN + 3], ik);
        atomicAdd(&sm[2 * NBIN + 4], pkk);
        atomicAdd(&sm[2 * NBIN + 5], gkk);
    }
    __syncthreads();

    for (int i = tid; i < 2 * NBIN + 6; i += NTH)
        atomicAdd(&g_scratch[b * SSTR + i], sm[i]);
}

__global__ void pan_final(float* __restrict__ out) {
    const int b = threadIdx.x;     // 32 threads, 16 active
    float lr = 0.f, lk = 0.f, lagg = 0.f, ldis = 0.f;

    if (b < NB) {
        const float* s = &g_scratch[b * SSTR];
        float ct[NSEG], ck[NSEG], T2[NSEG], K2[NSEG];
        #pragma unroll
        for (int i = 0; i < NSEG; i++) { ct[i] = 0.f; ck[i] = 0.f; T2[i] = 0.f; K2[i] = 0.f; }
        #pragma unroll
        for (int t = 0; t < NSEG; t++) {
            #pragma unroll
            for (int k = 0; k < NSEG; k++) {
                float ps = s[t * NSEG + k];
                float pc = s[NBIN + t * NSEG + k];
                T2[t] += ps;  K2[k] += ps;
                ct[t] += pc;  ck[k] += pc;
            }
        }

        float ir  = s[2 * NBIN + 0], prr = s[2 * NBIN + 1], grr = s[2 * NBIN + 2];
        float ikk = s[2 * NBIN + 3], pkk = s[2 * NBIN + 4], gkk = s[2 * NBIN + 5];
        lr = 1.0f - (2.0f * ir  + EPSF) / ((prr + EPSF) + (grr + EPSF));
        lk = 1.0f - (2.0f * ikk + EPSF) / ((pkk + EPSF) + (gkk + EPSF));

        float a[8];
        #pragma unroll
        for (int i = 1; i < NSEG; i++) {
            float inv = 1.0f / (ck[i] + 1.0f);
            float Ss  = s[i * NSEG + i];
            float n2  = T2[i] - (2.0f * inv - inv * inv) * Ss + inv * inv * (K2[i] - Ss);
            float nrm = sqrtf(fmaxf(n2, 0.0f));
            float d   = nrm - 0.5f;                       // SIGMA_AGG (no clamp, per reference)
            lagg += logf(d * d + 1.0f) / (ct[i] + 1.0f);
            float c1 = ck[i] + 0.001f;
            a[i - 1] = K2[i] / (c1 * c1);
        }
        #pragma unroll
        for (int i = 0; i < 8; i++) {
            #pragma unroll
            for (int j = i + 1; j < 8; j++) {
                float pr_ = 3.0f - sqrtf(a[i] + a[j]);    // SIGMA_DIS
                ldis += logf(pr_ * pr_ + 1.0f);
            }
        }
        ldis *= (1.0f / 56.0f);                            // K_MAX*(K_MAX-1)
    }

    #pragma unroll
    for (int o = 16; o; o >>= 1) {
        lr   += __shfl_down_sync(0xffffffffu, lr,   o);
        lk   += __shfl_down_sync(0xffffffffu, lk,   o);
        lagg += __shfl_down_sync(0xffffffffu, lagg, o);
        ldis += __shfl_down_sync(0xffffffffu, ldis, o);
    }
    if (b == 0) {
        out[0] = lr + 0.5f * lk + 0.25f * (lagg + ldis);   // ALPHA=0.5, BETA=0.25
        out[1] = lr;
        out[2] = lk;
        out[3] = lagg;
        out[4] = ldis;
    }
}

extern "C" void kernel_launch(void* const* d_in, const int* in_sizes, int n_in,
                              void* d_out, int out_size) {
    (void)in_sizes; (void)n_in; (void)out_size;
    pan_zero<<<1, 256>>>();
    dim3 grid(BPB, NB);
    pan_main<<<grid, NTH>>>(
        (const float4*)d_in[0], (const float4*)d_in[1],
        (const float4*)d_in[2], (const float4*)d_in[3],
        (const float4*)d_in[4],
        (const int4*)d_in[5],  (const int4*)d_in[6]);
    pan_final<<<1, 32>>>((float*)d_out);
}